// round 1
// baseline (speedup 1.0000x reference)
#include <cuda_runtime.h>

// Shapes (fixed by the problem)
#define BB 16
#define NNODE 512
#define MNB 16
#define HH 8
#define DD 128
#define BN 8192     // BB*NNODE
#define HD 1024     // HH*DD
#define FFD 256

// Scratch (device globals; no runtime allocation)
__device__ float g_Wh[(size_t)BN * HD];     // [node][h*128+e]
__device__ float g_ssrc[(size_t)BN * HH];
__device__ float g_sdst[(size_t)BN * HH];
__device__ float g_agg[(size_t)BN * HD];
__device__ float g_t[(size_t)BN * DD];
__device__ float g_u[(size_t)BN * FFD];

__device__ __forceinline__ float warp_sum(float v) {
#pragma unroll
    for (int o = 16; o > 0; o >>= 1) v += __shfl_xor_sync(0xffffffffu, v, o);
    return v;
}

// ---------------------------------------------------------------------------
// K1: Wh[node,h,:] = h[node,:] @ W[h]; fused s_src/s_dst = Wh . a_src/a_dst.
// grid (256 node-tiles of 32, 8 heads), 256 threads, 4x4 register tile.
// ---------------------------------------------------------------------------
__global__ void __launch_bounds__(256) k1_wh(
    const float* __restrict__ h, const float* __restrict__ W,
    const float* __restrict__ a_src, const float* __restrict__ a_dst)
{
    __shared__ float As[128 * 40];   // As[d*40 + r], rows of 4 floats 16B-aligned
    __shared__ float Ws[32 * 128];   // Ws[k*128 + e]

    const int tx = threadIdx.x;
    const int lane = tx & 31;
    const int trow = tx >> 5;
    const int n0 = blockIdx.x * 32;
    const int head = blockIdx.y;

    // A tile transposed: As[d][r] = h[(n0+r)*128 + d]  (coalesced global reads)
    for (int idx = tx; idx < 32 * 128; idx += 256) {
        int r = idx >> 7, d = idx & 127;
        As[d * 40 + r] = h[(size_t)(n0 + r) * 128 + d];
    }

    float acc[4][4];
#pragma unroll
    for (int i = 0; i < 4; i++)
#pragma unroll
        for (int j = 0; j < 4; j++) acc[i][j] = 0.f;

    const float* Whead = W + (size_t)head * 128 * 128;

    for (int k0 = 0; k0 < 128; k0 += 32) {
        __syncthreads();
        for (int idx = tx; idx < 32 * 128; idx += 256) {
            Ws[idx] = Whead[(size_t)(k0 << 7) + idx];   // (k0+k)*128 + e
        }
        __syncthreads();
#pragma unroll
        for (int k = 0; k < 32; ++k) {
            const float4 w = *(const float4*)(Ws + k * 128 + lane * 4);
            const float4 a = *(const float4*)(As + (k0 + k) * 40 + trow * 4);
            const float av[4] = {a.x, a.y, a.z, a.w};
            const float wv[4] = {w.x, w.y, w.z, w.w};
#pragma unroll
            for (int i = 0; i < 4; i++)
#pragma unroll
                for (int j = 0; j < 4; j++)
                    acc[i][j] = fmaf(av[i], wv[j], acc[i][j]);
        }
    }

    const float4 asv = *(const float4*)(a_src + head * 128 + lane * 4);
    const float4 adv = *(const float4*)(a_dst + head * 128 + lane * 4);

#pragma unroll
    for (int i = 0; i < 4; i++) {
        const int row = n0 + trow * 4 + i;
        float4 c = make_float4(acc[i][0], acc[i][1], acc[i][2], acc[i][3]);
        *(float4*)(g_Wh + (size_t)row * HD + head * 128 + lane * 4) = c;
        float ps = c.x * asv.x + c.y * asv.y + c.z * asv.z + c.w * asv.w;
        float pd = c.x * adv.x + c.y * adv.y + c.z * adv.z + c.w * adv.w;
        ps = warp_sum(ps);
        pd = warp_sum(pd);
        if (lane == 0) {
            g_ssrc[(size_t)row * HH + head] = ps;
            g_sdst[(size_t)row * HH + head] = pd;
        }
    }
}

// ---------------------------------------------------------------------------
// K2: attention (leaky_relu + mask + softmax over M) and neighbor aggregation.
// One block per node; 256 threads; float4 gather from L2-resident g_Wh.
// ---------------------------------------------------------------------------
__global__ void __launch_bounds__(256) k2_attn(
    const int* __restrict__ adj, const int* __restrict__ nlist)
{
    const int node = blockIdx.x;
    const int b = node >> 9;
    const int tx = threadIdx.x;

    __shared__ int   nls[MNB];
    __shared__ int   adjs[MNB];
    __shared__ float es[MNB][HH];
    __shared__ float attn_s[MNB][HH];

    if (tx < MNB) {
        nls[tx]  = nlist[(size_t)node * MNB + tx];
        adjs[tx] = adj[(size_t)node * MNB + tx];
    }
    __syncthreads();

    if (tx < MNB * HH) {
        const int m = tx >> 3, hh = tx & 7;
        float v = g_ssrc[(size_t)node * HH + hh]
                + g_sdst[(size_t)((b << 9) + nls[m]) * HH + hh];
        v = v > 0.f ? v : 0.2f * v;            // leaky_relu
        if (adjs[m] <= 0) v = -1e9f;           // mask
        es[m][hh] = v;
    }
    __syncthreads();

    if (tx < HH) {
        float mx = -3.4e38f;
#pragma unroll
        for (int m = 0; m < MNB; m++) mx = fmaxf(mx, es[m][tx]);
        float ex[MNB], s = 0.f;
#pragma unroll
        for (int m = 0; m < MNB; m++) { ex[m] = expf(es[m][tx] - mx); s += ex[m]; }
        const float inv = 1.f / s;
#pragma unroll
        for (int m = 0; m < MNB; m++) attn_s[m][tx] = ex[m] * inv;
    }
    __syncthreads();

    // Each thread owns 4 consecutive output elements (one head slice per 32 threads)
    const int hh = tx >> 5;
    const float4* whb = (const float4*)g_Wh + (size_t)(b << 9) * 256;
    float4 acc = make_float4(0.f, 0.f, 0.f, 0.f);
#pragma unroll
    for (int m = 0; m < MNB; m++) {
        const float wgt = attn_s[m][hh];
        const float4 v = whb[(size_t)nls[m] * 256 + tx];
        acc.x = fmaf(wgt, v.x, acc.x);
        acc.y = fmaf(wgt, v.y, acc.y);
        acc.z = fmaf(wgt, v.z, acc.z);
        acc.w = fmaf(wgt, v.w, acc.w);
    }
    ((float4*)g_agg)[(size_t)node * 256 + tx] = acc;
}

// ---------------------------------------------------------------------------
// K3: y = agg @ Wo  (+ h residual), LayerNorm1 -> g_t.
// grid 256 (32 rows each), 256 threads, 4x4 tile, K=1024 chunked by 32.
// ---------------------------------------------------------------------------
__global__ void __launch_bounds__(256) k3_proj_ln1(
    const float* __restrict__ h, const float* __restrict__ Wo,
    const float* __restrict__ g1, const float* __restrict__ b1)
{
    __shared__ float As[32 * 40];
    __shared__ float Ws[32 * 128];

    const int tx = threadIdx.x;
    const int lane = tx & 31;
    const int trow = tx >> 5;
    const int n0 = blockIdx.x * 32;

    float acc[4][4];
#pragma unroll
    for (int i = 0; i < 4; i++)
#pragma unroll
        for (int j = 0; j < 4; j++) acc[i][j] = 0.f;

    for (int k0 = 0; k0 < HD; k0 += 32) {
        for (int idx = tx; idx < 32 * 32; idx += 256) {
            int r = idx >> 5, k = idx & 31;
            As[k * 40 + r] = g_agg[(size_t)(n0 + r) * HD + k0 + k];
        }
        for (int idx = tx; idx < 32 * 128; idx += 256) {
            int k = idx >> 7, e = idx & 127;
            Ws[idx] = Wo[(size_t)(k0 + k) * 128 + e];
        }
        __syncthreads();
#pragma unroll
        for (int k = 0; k < 32; ++k) {
            const float4 w = *(const float4*)(Ws + k * 128 + lane * 4);
            const float4 a = *(const float4*)(As + k * 40 + trow * 4);
            const float av[4] = {a.x, a.y, a.z, a.w};
            const float wv[4] = {w.x, w.y, w.z, w.w};
#pragma unroll
            for (int i = 0; i < 4; i++)
#pragma unroll
                for (int j = 0; j < 4; j++)
                    acc[i][j] = fmaf(av[i], wv[j], acc[i][j]);
        }
        __syncthreads();
    }

    const float4 gg = *(const float4*)(g1 + lane * 4);
    const float4 bb = *(const float4*)(b1 + lane * 4);

#pragma unroll
    for (int i = 0; i < 4; i++) {
        const int row = n0 + trow * 4 + i;
        const float4 hv = *(const float4*)(h + (size_t)row * 128 + lane * 4);
        float x0 = acc[i][0] + hv.x, x1 = acc[i][1] + hv.y;
        float x2 = acc[i][2] + hv.z, x3 = acc[i][3] + hv.w;
        const float mu = warp_sum(x0 + x1 + x2 + x3) * (1.f / 128.f);
        x0 -= mu; x1 -= mu; x2 -= mu; x3 -= mu;
        const float var = warp_sum(x0 * x0 + x1 * x1 + x2 * x2 + x3 * x3) * (1.f / 128.f);
        const float rs = rsqrtf(var + 1e-5f);
        float4 y;
        y.x = x0 * rs * gg.x + bb.x;
        y.y = x1 * rs * gg.y + bb.y;
        y.z = x2 * rs * gg.z + bb.z;
        y.w = x3 * rs * gg.w + bb.w;
        *(float4*)(g_t + (size_t)row * 128 + lane * 4) = y;
    }
}

// ---------------------------------------------------------------------------
// K4a: u = relu(t @ ff_w1 + b1) -> g_u.  [8192,128]@[128,256]
// grid 256, 256 threads, 4x8 tile, K=128 in smem, W1 chunked BK=16.
// ---------------------------------------------------------------------------
__global__ void __launch_bounds__(256) k4a_ff1(
    const float* __restrict__ w1, const float* __restrict__ bb1)
{
    __shared__ float Ts[128 * 40];
    __shared__ float W1s[16 * 256];

    const int tx = threadIdx.x;
    const int lane = tx & 31;
    const int trow = tx >> 5;
    const int n0 = blockIdx.x * 32;

    for (int idx = tx; idx < 32 * 128; idx += 256) {
        int r = idx >> 7, k = idx & 127;
        Ts[k * 40 + r] = g_t[(size_t)(n0 + r) * 128 + k];
    }

    float acc[4][8];
#pragma unroll
    for (int i = 0; i < 4; i++)
#pragma unroll
        for (int j = 0; j < 8; j++) acc[i][j] = 0.f;

    for (int k0 = 0; k0 < 128; k0 += 16) {
        __syncthreads();
        for (int idx = tx; idx < 16 * 256; idx += 256) {
            W1s[idx] = w1[(size_t)(k0 << 8) + idx];   // (k0+k)*256 + c
        }
        __syncthreads();
#pragma unroll
        for (int k = 0; k < 16; ++k) {
            const float4 a = *(const float4*)(Ts + (k0 + k) * 40 + trow * 4);
            const float4 w0 = *(const float4*)(W1s + k * 256 + lane * 8);
            const float4 w1v = *(const float4*)(W1s + k * 256 + lane * 8 + 4);
            const float av[4] = {a.x, a.y, a.z, a.w};
            const float wv[8] = {w0.x, w0.y, w0.z, w0.w, w1v.x, w1v.y, w1v.z, w1v.w};
#pragma unroll
            for (int i = 0; i < 4; i++)
#pragma unroll
                for (int j = 0; j < 8; j++)
                    acc[i][j] = fmaf(av[i], wv[j], acc[i][j]);
        }
    }

    const float4 bA = *(const float4*)(bb1 + lane * 8);
    const float4 bBv = *(const float4*)(bb1 + lane * 8 + 4);
    const float bv[8] = {bA.x, bA.y, bA.z, bA.w, bBv.x, bBv.y, bBv.z, bBv.w};

#pragma unroll
    for (int i = 0; i < 4; i++) {
        const int row = n0 + trow * 4 + i;
        float4 u0, u1;
        u0.x = fmaxf(acc[i][0] + bv[0], 0.f);
        u0.y = fmaxf(acc[i][1] + bv[1], 0.f);
        u0.z = fmaxf(acc[i][2] + bv[2], 0.f);
        u0.w = fmaxf(acc[i][3] + bv[3], 0.f);
        u1.x = fmaxf(acc[i][4] + bv[4], 0.f);
        u1.y = fmaxf(acc[i][5] + bv[5], 0.f);
        u1.z = fmaxf(acc[i][6] + bv[6], 0.f);
        u1.w = fmaxf(acc[i][7] + bv[7], 0.f);
        ((float4*)g_u)[(size_t)row * 64 + lane * 2]     = u0;
        ((float4*)g_u)[(size_t)row * 64 + lane * 2 + 1] = u1;
    }
}

// ---------------------------------------------------------------------------
// K4b: y = u @ ff_w2 + b2 + t, LayerNorm2 -> out.  [8192,256]@[256,128]
// ---------------------------------------------------------------------------
__global__ void __launch_bounds__(256) k4b_ff2_ln2(
    const float* __restrict__ w2, const float* __restrict__ bb2,
    const float* __restrict__ g2, const float* __restrict__ be2,
    float* __restrict__ out)
{
    __shared__ float As[32 * 40];
    __shared__ float Ws[32 * 128];

    const int tx = threadIdx.x;
    const int lane = tx & 31;
    const int trow = tx >> 5;
    const int n0 = blockIdx.x * 32;

    float acc[4][4];
#pragma unroll
    for (int i = 0; i < 4; i++)
#pragma unroll
        for (int j = 0; j < 4; j++) acc[i][j] = 0.f;

    for (int k0 = 0; k0 < FFD; k0 += 32) {
        for (int idx = tx; idx < 32 * 32; idx += 256) {
            int r = idx >> 5, k = idx & 31;
            As[k * 40 + r] = g_u[(size_t)(n0 + r) * FFD + k0 + k];
        }
        for (int idx = tx; idx < 32 * 128; idx += 256) {
            int k = idx >> 7, e = idx & 127;
            Ws[idx] = w2[(size_t)(k0 + k) * 128 + e];
        }
        __syncthreads();
#pragma unroll
        for (int k = 0; k < 32; ++k) {
            const float4 w = *(const float4*)(Ws + k * 128 + lane * 4);
            const float4 a = *(const float4*)(As + k * 40 + trow * 4);
            const float av[4] = {a.x, a.y, a.z, a.w};
            const float wv[4] = {w.x, w.y, w.z, w.w};
#pragma unroll
            for (int i = 0; i < 4; i++)
#pragma unroll
                for (int j = 0; j < 4; j++)
                    acc[i][j] = fmaf(av[i], wv[j], acc[i][j]);
        }
        __syncthreads();
    }

    const float4 b2v = *(const float4*)(bb2 + lane * 4);
    const float4 gg = *(const float4*)(g2 + lane * 4);
    const float4 bb = *(const float4*)(be2 + lane * 4);

#pragma unroll
    for (int i = 0; i < 4; i++) {
        const int row = n0 + trow * 4 + i;
        const float4 tv = *(const float4*)(g_t + (size_t)row * 128 + lane * 4);
        float x0 = acc[i][0] + b2v.x + tv.x;
        float x1 = acc[i][1] + b2v.y + tv.y;
        float x2 = acc[i][2] + b2v.z + tv.z;
        float x3 = acc[i][3] + b2v.w + tv.w;
        const float mu = warp_sum(x0 + x1 + x2 + x3) * (1.f / 128.f);
        x0 -= mu; x1 -= mu; x2 -= mu; x3 -= mu;
        const float var = warp_sum(x0 * x0 + x1 * x1 + x2 * x2 + x3 * x3) * (1.f / 128.f);
        const float rs = rsqrtf(var + 1e-5f);
        float4 y;
        y.x = x0 * rs * gg.x + bb.x;
        y.y = x1 * rs * gg.y + bb.y;
        y.z = x2 * rs * gg.z + bb.z;
        y.w = x3 * rs * gg.w + bb.w;
        *(float4*)(out + (size_t)row * 128 + lane * 4) = y;
    }
}

// ---------------------------------------------------------------------------
extern "C" void kernel_launch(void* const* d_in, const int* in_sizes, int n_in,
                              void* d_out, int out_size)
{
    const float* h     = (const float*)d_in[0];
    const int*   adj   = (const int*)d_in[1];
    const int*   nlist = (const int*)d_in[2];
    const float* W     = (const float*)d_in[3];
    const float* a_src = (const float*)d_in[4];
    const float* a_dst = (const float*)d_in[5];
    const float* Wo    = (const float*)d_in[6];
    const float* ln1g  = (const float*)d_in[7];
    const float* ln1b  = (const float*)d_in[8];
    const float* w1    = (const float*)d_in[9];
    const float* b1    = (const float*)d_in[10];
    const float* w2    = (const float*)d_in[11];
    const float* b2    = (const float*)d_in[12];
    const float* ln2g  = (const float*)d_in[13];
    const float* ln2b  = (const float*)d_in[14];
    float* out = (float*)d_out;

    k1_wh<<<dim3(BN / 32, HH), 256>>>(h, W, a_src, a_dst);
    k2_attn<<<BN, 256>>>(adj, nlist);
    k3_proj_ln1<<<BN / 32, 256>>>(h, Wo, ln1g, ln1b);
    k4a_ff1<<<BN / 32, 256>>>(w1, b1);
    k4b_ff2_ln2<<<BN / 32, 256>>>(w2, b2, ln2g, ln2b, out);
}